// round 2
// baseline (speedup 1.0000x reference)
#include <cuda_runtime.h>
#include <math.h>

namespace {
constexpr int B_ = 64;
constexpr int T_ = 512;
constexpr int I_ = 512;
constexpr int H_ = 1024;
constexpr int G_ = 3 * H_;     // 3072
constexpr int NBLK = 128;      // persistent blocks (<=148 SMs, all resident)
constexpr int NTHR = 256;
constexpr int PW = 36;         // ws row pad (floats)
constexpr int PG = 25;         // hg_s row pad
constexpr int BH = B_ * H_;
// dynamic smem partition (floats)
constexpr int WS_F = 1024 * PW;          // 36864
constexpr int HS_F = 2 * 64 * 64;        // 8192
constexpr int HG_F = 64 * PG;            // 1600
constexpr int SMEM_BYTES = (WS_F + HS_F + HG_F) * 4;  // 186624
}

// Scratch (device globals -- no runtime allocation)
__device__ float g_xg[(size_t)B_ * T_ * G_];    // xg for current layer
__device__ float g_hseq[(size_t)B_ * T_ * H_];  // layer-0 hidden sequence
__device__ float g_h1[2 * BH];                  // layer-1 h ping-pong
__device__ unsigned g_barcnt[2 * T_];           // grid-barrier counters

// ---- packed f32x2 helpers ----
__device__ __forceinline__ unsigned long long dup2(float v) {
    unsigned long long r;
    asm("mov.b64 %0, {%1, %1};" : "=l"(r) : "f"(v));
    return r;
}
__device__ __forceinline__ void fma2(unsigned long long &d, unsigned long long a, unsigned long long b) {
    asm("fma.rn.f32x2 %0, %1, %2, %0;" : "+l"(d) : "l"(a), "l"(b));
}
__device__ __forceinline__ float2 unp2(unsigned long long v) {
    float2 f;
    asm("mov.b64 {%0, %1}, %2;" : "=f"(f.x), "=f"(f.y) : "l"(v));
    return f;
}

// ---- grid barrier (counter array, reset each replay by reset kernel) ----
__device__ __forceinline__ void grid_bar(unsigned* cnt) {
    __threadfence();
    __syncthreads();
    if (threadIdx.x == 0) {
        asm volatile("red.release.gpu.global.add.u32 [%0], 1;" :: "l"(cnt) : "memory");
        unsigned v;
        do {
            asm volatile("ld.acquire.gpu.global.u32 %0, [%1];" : "=r"(v) : "l"(cnt) : "memory");
        } while (v < (unsigned)NBLK);
    }
    __syncthreads();
}

__global__ void reset_barriers() {
    g_barcnt[threadIdx.x] = 0;   // 1024 threads
}

// ============================================================================
// xg = A[M][K] @ W[G][K]^T + b_ih + (b_hh folded for r/z gates only)
// ============================================================================
__global__ __launch_bounds__(256) void sgemm_bias(
    const float* __restrict__ A_ext, int use_hseq,
    const float* __restrict__ W,
    const float* __restrict__ bih, const float* __restrict__ bhh,
    int K)
{
    const float* __restrict__ A = use_hseq ? (const float*)g_hseq : A_ext;
    __shared__ __align__(16) float As[16][128];
    __shared__ __align__(16) float Ws[16][128];

    const int tid = threadIdx.x;
    const int m0 = blockIdx.y * 128;
    const int n0 = blockIdx.x * 128;
    const int tm = (tid >> 4) << 3;
    const int tn = (tid & 15) << 3;

    unsigned long long acc[8][4];
#pragma unroll
    for (int i = 0; i < 8; i++)
#pragma unroll
        for (int j = 0; j < 4; j++) acc[i][j] = 0ull;

    for (int k0 = 0; k0 < K; k0 += 16) {
#pragma unroll
        for (int r = 0; r < 2; r++) {
            int f = tid + 256 * r;
            int row = f >> 2;
            int c4 = (f & 3) << 2;
            float4 va = *reinterpret_cast<const float4*>(A + (size_t)(m0 + row) * K + k0 + c4);
            As[c4 + 0][row] = va.x; As[c4 + 1][row] = va.y;
            As[c4 + 2][row] = va.z; As[c4 + 3][row] = va.w;
            float4 vw = *reinterpret_cast<const float4*>(W + (size_t)(n0 + row) * K + k0 + c4);
            Ws[c4 + 0][row] = vw.x; Ws[c4 + 1][row] = vw.y;
            Ws[c4 + 2][row] = vw.z; Ws[c4 + 3][row] = vw.w;
        }
        __syncthreads();
#pragma unroll
        for (int k = 0; k < 16; k++) {
            float4 a0 = *reinterpret_cast<const float4*>(&As[k][tm]);
            float4 a1 = *reinterpret_cast<const float4*>(&As[k][tm + 4]);
            ulonglong2 w0 = *reinterpret_cast<const ulonglong2*>(&Ws[k][tn]);
            ulonglong2 w1 = *reinterpret_cast<const ulonglong2*>(&Ws[k][tn + 4]);
            float av[8] = {a0.x, a0.y, a0.z, a0.w, a1.x, a1.y, a1.z, a1.w};
#pragma unroll
            for (int i = 0; i < 8; i++) {
                unsigned long long ad = dup2(av[i]);
                fma2(acc[i][0], ad, w0.x);
                fma2(acc[i][1], ad, w0.y);
                fma2(acc[i][2], ad, w1.x);
                fma2(acc[i][3], ad, w1.y);
            }
        }
        __syncthreads();
    }

#pragma unroll
    for (int i = 0; i < 8; i++) {
        float o[8];
#pragma unroll
        for (int j = 0; j < 4; j++) { float2 p = unp2(acc[i][j]); o[2 * j] = p.x; o[2 * j + 1] = p.y; }
#pragma unroll
        for (int j = 0; j < 8; j++) {
            int nn = n0 + tn + j;
            o[j] += bih[nn] + (nn < 2 * H_ ? bhh[nn] : 0.f);
        }
        float* cp = g_xg + (size_t)(m0 + tm + i) * G_ + n0 + tn;
        reinterpret_cast<float4*>(cp)[0] = make_float4(o[0], o[1], o[2], o[3]);
        reinterpret_cast<float4*>(cp)[1] = make_float4(o[4], o[5], o[6], o[7]);
    }
}

// ============================================================================
// Persistent recurrence kernel: one layer, all 512 steps.
// Block bid owns j columns [bid*8, bid*8+8) and their 3 gate rows of Whh
// (24 rows, resident in smem). Per step: hg = h_{t-1} @ Whh_sub^T (in-block
// 16-way k-split, shfl reduce), then gates computed locally, one grid barrier.
// ============================================================================
__global__ void __launch_bounds__(NTHR, 1) gru_recurrent(
    const float* __restrict__ Whh, const float* __restrict__ bhh,
    int layer, float* __restrict__ final_out)
{
    extern __shared__ float sm[];
    float* ws = sm;                    // [1024][PW] swizzled
    float* hs = sm + WS_F;             // [2][64][64] swizzled transposed h chunk
    float* hgs = sm + WS_F + HS_F;     // [64][PG]

    const int tid = threadIdx.x;
    const int bid = blockIdx.x;
    const int j0 = bid * 8;
    const int kg = tid & 15;           // k-split group
    const int wi = tid >> 4;           // worker 0..15
    const int mi = wi & 7, nj = wi >> 3;
    const int m0 = mi * 8;
    const int n0 = nj * 12;

    // ---- load block's 24 Whh rows into swizzled smem (once) ----
    for (int f = tid; f < 24 * 256; f += NTHR) {
        int v = f >> 8;                 // vcol 0..23
        int q = f & 255;                // float4 index along k
        int n = ((v >> 3) << 10) + j0 + (v & 7);
        float4 w4 = *reinterpret_cast<const float4*>(Whh + (size_t)n * H_ + (q << 2));
        int k = q << 2;
        int xw = (q & 7) << 2;
        int nn = ((v & ~3) ^ xw) + (v & 3);
        float* wr = ws + (size_t)k * PW;
        wr[0 * PW + nn] = w4.x;
        wr[1 * PW + nn] = w4.y;
        wr[2 * PW + nn] = w4.z;
        wr[3 * PW + nn] = w4.w;
    }
    const float bhn = bhh[2 * H_ + j0 + ((tid * 2) & 7)];       // for gate e=0
    const float bhn1 = bhh[2 * H_ + j0 + ((tid * 2 + 1) & 7)];  // for gate e=1
    __syncthreads();

    unsigned* barBase = g_barcnt + layer * T_;

    for (int t = 0; t < T_; t++) {
        float gr[2] = {0.f, 0.f}, gz[2] = {0.f, 0.f}, gn[2] = {0.f, 0.f};

        if (t > 0) {
            const float* hre;
            size_t hstr;
            if (layer == 0) { hre = g_hseq + (size_t)(t - 1) * H_; hstr = (size_t)T_ * H_; }
            else            { hre = g_h1 + (size_t)((t - 1) & 1) * BH; hstr = H_; }

            unsigned long long acc[8][6];
#pragma unroll
            for (int i = 0; i < 8; i++)
#pragma unroll
                for (int p = 0; p < 6; p++) acc[i][p] = 0ull;

            // preload chunk 0
            {
#pragma unroll
                for (int r = 0; r < 4; r++) {
                    int f = tid + NTHR * r;
                    int m = f >> 4, q = f & 15;
                    float4 v = *reinterpret_cast<const float4*>(hre + (size_t)m * hstr + (q << 2));
                    float* d = hs;  // buf 0
                    int x = q << 2;
                    d[(4 * q + 0) * 64 + (m ^ x)] = v.x;
                    d[(4 * q + 1) * 64 + (m ^ x)] = v.y;
                    d[(4 * q + 2) * 64 + (m ^ x)] = v.z;
                    d[(4 * q + 3) * 64 + (m ^ x)] = v.w;
                }
            }
            __syncthreads();

            for (int c = 0; c < 16; c++) {
                float4 ld[4];
                if (c < 15) {
#pragma unroll
                    for (int r = 0; r < 4; r++) {
                        int f = tid + NTHR * r;
                        int m = f >> 4, q = f & 15;
                        ld[r] = *reinterpret_cast<const float4*>(
                            hre + (size_t)m * hstr + (c + 1) * 64 + (q << 2));
                    }
                }
                const float* hb = hs + (c & 1) * (64 * 64);
                const int kb = c * 64 + kg * 4;
                const int xh = kg << 2;
#pragma unroll
                for (int j = 0; j < 4; j++) {
                    int k = kb + j;
                    int kk = k & 63;
                    const float* hrow = hb + (size_t)kk * 64;
                    float4 ha = *reinterpret_cast<const float4*>(hrow + (m0 ^ xh));
                    float4 hc = *reinterpret_cast<const float4*>(hrow + ((m0 + 4) ^ xh));
                    const float* wr = ws + (size_t)k * PW;
                    int xw = ((k >> 2) & 7) << 2;
                    ulonglong2 wa = *reinterpret_cast<const ulonglong2*>(wr + (n0 ^ xw));
                    ulonglong2 wb = *reinterpret_cast<const ulonglong2*>(wr + ((n0 + 4) ^ xw));
                    ulonglong2 wc = *reinterpret_cast<const ulonglong2*>(wr + ((n0 + 8) ^ xw));
                    float hv[8] = {ha.x, ha.y, ha.z, ha.w, hc.x, hc.y, hc.z, hc.w};
#pragma unroll
                    for (int i = 0; i < 8; i++) {
                        unsigned long long ad = dup2(hv[i]);
                        fma2(acc[i][0], ad, wa.x);
                        fma2(acc[i][1], ad, wa.y);
                        fma2(acc[i][2], ad, wb.x);
                        fma2(acc[i][3], ad, wb.y);
                        fma2(acc[i][4], ad, wc.x);
                        fma2(acc[i][5], ad, wc.y);
                    }
                }
                if (c < 15) {
                    float* d = hs + ((c + 1) & 1) * (64 * 64);
#pragma unroll
                    for (int r = 0; r < 4; r++) {
                        int f = tid + NTHR * r;
                        int m = f >> 4, q = f & 15;
                        int x = q << 2;
                        d[(4 * q + 0) * 64 + (m ^ x)] = ld[r].x;
                        d[(4 * q + 1) * 64 + (m ^ x)] = ld[r].y;
                        d[(4 * q + 2) * 64 + (m ^ x)] = ld[r].z;
                        d[(4 * q + 3) * 64 + (m ^ x)] = ld[r].w;
                    }
                }
                __syncthreads();
            }

            // ---- butterfly reduce over kg (lane bits 0..3), write hg_s ----
#pragma unroll
            for (int i = 0; i < 8; i++) {
#pragma unroll
                for (int p = 0; p < 6; p++) {
                    float2 v = unp2(acc[i][p]);
#pragma unroll
                    for (int msk = 1; msk < 16; msk <<= 1) {
                        v.x += __shfl_xor_sync(0xffffffffu, v.x, msk);
                        v.y += __shfl_xor_sync(0xffffffffu, v.y, msk);
                    }
                    if (kg == 0) {
                        hgs[(m0 + i) * PG + n0 + 2 * p] = v.x;
                        hgs[(m0 + i) * PG + n0 + 2 * p + 1] = v.y;
                    }
                }
            }
            __syncthreads();

            int idx = tid * 2;
#pragma unroll
            for (int e = 0; e < 2; e++) {
                int b = (idx + e) >> 3, jj = (idx + e) & 7;
                gr[e] = hgs[b * PG + jj];
                gz[e] = hgs[b * PG + 8 + jj];
                gn[e] = hgs[b * PG + 16 + jj];
            }
        }

        // ---- gates: 512 outputs per block, 2 per thread ----
        int idx = tid * 2;
#pragma unroll
        for (int e = 0; e < 2; e++) {
            int b = (idx + e) >> 3, jj = (idx + e) & 7;
            int col = j0 + jj;
            const float* xp = g_xg + ((size_t)b * T_ + t) * G_ + col;
            float xr = xp[0], xz = xp[H_], xn = xp[2 * H_];
            float r = 1.f / (1.f + expf(-(xr + gr[e])));
            float z = 1.f / (1.f + expf(-(xz + gz[e])));
            float bn = e ? bhn1 : bhn;
            float n = tanhf(xn + r * (gn[e] + bn));
            float hp = 0.f;
            if (t > 0) {
                hp = (layer == 0) ? g_hseq[((size_t)b * T_ + (t - 1)) * H_ + col]
                                  : g_h1[(size_t)((t - 1) & 1) * BH + (size_t)b * H_ + col];
            }
            float hnew = (1.f - z) * n + z * hp;
            if (layer == 0) {
                g_hseq[((size_t)b * T_ + t) * H_ + col] = hnew;
            } else if (t == T_ - 1) {
                final_out[(size_t)b * H_ + col] = hnew;
            } else {
                g_h1[(size_t)(t & 1) * BH + (size_t)b * H_ + col] = hnew;
            }
        }

        if (t < T_ - 1) grid_bar(barBase + t);
    }
}

// ============================================================================
extern "C" void kernel_launch(void* const* d_in, const int* in_sizes, int n_in,
                              void* d_out, int out_size)
{
    const float* x    = (const float*)d_in[0];
    const float* wih0 = (const float*)d_in[1];
    const float* whh0 = (const float*)d_in[2];
    const float* bih0 = (const float*)d_in[3];
    const float* bhh0 = (const float*)d_in[4];
    const float* wih1 = (const float*)d_in[5];
    const float* whh1 = (const float*)d_in[6];
    const float* bih1 = (const float*)d_in[7];
    const float* bhh1 = (const float*)d_in[8];
    float* out = (float*)d_out;

    cudaFuncSetAttribute(gru_recurrent, cudaFuncAttributeMaxDynamicSharedMemorySize, SMEM_BYTES);

    dim3 gg(G_ / 128, (B_ * T_) / 128);

    reset_barriers<<<1, 2 * T_>>>();

    sgemm_bias<<<gg, 256>>>(x, 0, wih0, bih0, bhh0, I_);
    gru_recurrent<<<NBLK, NTHR, SMEM_BYTES>>>(whh0, bhh0, 0, out);

    sgemm_bias<<<gg, 256>>>(nullptr, 1, wih1, bih1, bhh1, H_);
    gru_recurrent<<<NBLK, NTHR, SMEM_BYTES>>>(whh1, bhh1, 1, out);
}

// round 4
// speedup vs baseline: 1.4703x; 1.4703x over previous
#include <cuda_runtime.h>
#include <math.h>
#include <stdint.h>

namespace {
constexpr int B_ = 64;
constexpr int T_ = 512;
constexpr int I_ = 512;
constexpr int H_ = 1024;
constexpr int G_ = 3 * H_;     // 3072
constexpr int NBLK = 128;      // persistent blocks
constexpr int NTHR = 256;
constexpr int BH = B_ * H_;

constexpr int WS_PAD = 1028;   // W row pad (floats) -> bank stride 4
constexpr int AS_PAD = 68;     // h chunk row pad   -> bank stride 4
constexpr int RED_PAD = 25;
constexpr int WS_F  = 24 * WS_PAD;    // 24672
constexpr int AS_F  = 2 * 64 * AS_PAD; // 8704
constexpr int RED_F = 4 * 64 * RED_PAD; // 6400
constexpr int REC_SMEM = (WS_F + AS_F + RED_F) * 4;  // 159104 bytes
}

// Scratch (device globals -- no runtime allocation)
__device__ float g_xg[(size_t)B_ * T_ * G_];
__device__ float g_hseq[(size_t)B_ * T_ * H_];
__device__ float g_h1[2 * BH];
__device__ unsigned g_barcnt[2 * T_];

// ---- tf32 helpers ----
__device__ __forceinline__ uint32_t f2tf(float x) {
    uint32_t r;
    asm("cvt.rna.tf32.f32 %0, %1;" : "=r"(r) : "f"(x));
    return r;
}
__device__ __forceinline__ float4 cvt4(float4 v) {
    return make_float4(__uint_as_float(f2tf(v.x)), __uint_as_float(f2tf(v.y)),
                       __uint_as_float(f2tf(v.z)), __uint_as_float(f2tf(v.w)));
}
// m16n8k8 tf32 mma, D += A*B
__device__ __forceinline__ void mma8(float* d, const uint32_t* a, const uint32_t* b) {
    asm volatile(
        "mma.sync.aligned.m16n8k8.row.col.f32.tf32.tf32.f32 "
        "{%0,%1,%2,%3}, {%4,%5,%6,%7}, {%8,%9}, {%0,%1,%2,%3};"
        : "+f"(d[0]), "+f"(d[1]), "+f"(d[2]), "+f"(d[3])
        : "r"(a[0]), "r"(a[1]), "r"(a[2]), "r"(a[3]), "r"(b[0]), "r"(b[1]));
}

// ---- grid barrier ----
__device__ __forceinline__ void grid_bar(unsigned* cnt) {
    __threadfence();
    __syncthreads();
    if (threadIdx.x == 0) {
        asm volatile("red.release.gpu.global.add.u32 [%0], 1;" :: "l"(cnt) : "memory");
        unsigned v;
        do {
            asm volatile("ld.acquire.gpu.global.u32 %0, [%1];" : "=r"(v) : "l"(cnt) : "memory");
        } while (v < (unsigned)NBLK);
    }
    __syncthreads();
}

__global__ void reset_barriers() { g_barcnt[threadIdx.x] = 0; }

// ============================================================================
// xg = A[M][K] @ W[G][K]^T + b_ih (+ b_hh folded for r/z gates)
// tf32 mma.sync, tile 128x128x16, double buffered. 8 warps = 4m x 2n.
// ============================================================================
__global__ __launch_bounds__(256) void xg_gemm(
    const float* __restrict__ A_ext, int use_hseq,
    const float* __restrict__ W,
    const float* __restrict__ bih, const float* __restrict__ bhh,
    int K)
{
    __shared__ __align__(16) float sA[2][128][20];
    __shared__ __align__(16) float sB[2][128][20];
    const float* __restrict__ A = use_hseq ? (const float*)g_hseq : A_ext;

    const int tid = threadIdx.x;
    const int lane = tid & 31, wid = tid >> 5;
    const int g = lane >> 2, tig = lane & 3;
    const int wm = wid & 3, wn = wid >> 2;
    const int m0 = blockIdx.y * 128, n0 = blockIdx.x * 128;
    const int mrow = tid >> 1;
    const int kh = (tid & 1) * 8;

    float acc[2][8][4];
#pragma unroll
    for (int mi = 0; mi < 2; mi++)
#pragma unroll
        for (int ni = 0; ni < 8; ni++)
#pragma unroll
            for (int q = 0; q < 4; q++) acc[mi][ni][q] = 0.f;

    const int nch = K >> 4;
    // stage chunk 0
    {
        const float* ap = A + (size_t)(m0 + mrow) * K + kh;
        const float* bp = W + (size_t)(n0 + mrow) * K + kh;
        float4 a0 = *(const float4*)ap, a1 = *(const float4*)(ap + 4);
        float4 b0 = *(const float4*)bp, b1 = *(const float4*)(bp + 4);
        *(float4*)&sA[0][mrow][kh] = cvt4(a0);
        *(float4*)&sA[0][mrow][kh + 4] = cvt4(a1);
        *(float4*)&sB[0][mrow][kh] = cvt4(b0);
        *(float4*)&sB[0][mrow][kh + 4] = cvt4(b1);
    }
    __syncthreads();

    for (int ch = 0; ch < nch; ch++) {
        float4 la0, la1, lb0, lb1;
        if (ch + 1 < nch) {
            const float* ap = A + (size_t)(m0 + mrow) * K + (ch + 1) * 16 + kh;
            const float* bp = W + (size_t)(n0 + mrow) * K + (ch + 1) * 16 + kh;
            la0 = *(const float4*)ap; la1 = *(const float4*)(ap + 4);
            lb0 = *(const float4*)bp; lb1 = *(const float4*)(bp + 4);
        }
        const int buf = ch & 1;
#pragma unroll
        for (int s = 0; s < 2; s++) {
            const int k0 = s * 8;
            uint32_t af[2][4];
#pragma unroll
            for (int mi = 0; mi < 2; mi++) {
                int mb = wm * 32 + mi * 16;
                af[mi][0] = __float_as_uint(sA[buf][mb + g][k0 + tig]);
                af[mi][1] = __float_as_uint(sA[buf][mb + 8 + g][k0 + tig]);
                af[mi][2] = __float_as_uint(sA[buf][mb + g][k0 + tig + 4]);
                af[mi][3] = __float_as_uint(sA[buf][mb + 8 + g][k0 + tig + 4]);
            }
#pragma unroll
            for (int ni = 0; ni < 8; ni++) {
                int nb = wn * 64 + ni * 8;
                uint32_t bf[2];
                bf[0] = __float_as_uint(sB[buf][nb + g][k0 + tig]);
                bf[1] = __float_as_uint(sB[buf][nb + g][k0 + tig + 4]);
                mma8(acc[0][ni], af[0], bf);
                mma8(acc[1][ni], af[1], bf);
            }
        }
        if (ch + 1 < nch) {
            const int nb2 = buf ^ 1;
            *(float4*)&sA[nb2][mrow][kh] = cvt4(la0);
            *(float4*)&sA[nb2][mrow][kh + 4] = cvt4(la1);
            *(float4*)&sB[nb2][mrow][kh] = cvt4(lb0);
            *(float4*)&sB[nb2][mrow][kh + 4] = cvt4(lb1);
        }
        __syncthreads();
    }

    // epilogue: bias + store
#pragma unroll
    for (int mi = 0; mi < 2; mi++) {
        int m = m0 + wm * 32 + mi * 16 + g;
#pragma unroll
        for (int ni = 0; ni < 8; ni++) {
            int n = n0 + wn * 64 + ni * 8 + 2 * tig;
            float b0 = bih[n], b1 = bih[n + 1];
            if (n < 2 * H_) { b0 += bhh[n]; b1 += bhh[n + 1]; }
            *(float2*)(g_xg + (size_t)m * G_ + n) =
                make_float2(acc[mi][ni][0] + b0, acc[mi][ni][1] + b1);
            *(float2*)(g_xg + (size_t)(m + 8) * G_ + n) =
                make_float2(acc[mi][ni][2] + b0, acc[mi][ni][3] + b1);
        }
    }
}

// ============================================================================
// Persistent recurrence: block owns 8 hidden cols (24 Whh rows resident in
// smem as tf32). Per step: hg = h_{t-1} @ Whh_sub^T via mma.sync tf32,
// 8 warps = 2 m-halves x 4 k-quarters, smem reduce, gates, grid barrier.
// ============================================================================
__global__ void __launch_bounds__(NTHR, 1) gru_rec_mma(
    const float* __restrict__ Whh, const float* __restrict__ bhh,
    int layer, float* __restrict__ final_out)
{
    extern __shared__ float sm[];
    float* ws = sm;                 // [24][WS_PAD] tf32 bits
    float* as_ = sm + WS_F;         // [2][64][AS_PAD] tf32 bits
    float* red = sm + WS_F + AS_F;  // [4][64][RED_PAD]

    const int tid = threadIdx.x;
    const int lane = tid & 31, wid = tid >> 5;
    const int g = lane >> 2, tig = lane & 3;
    const int wm = wid >> 2;        // 0..1  (m half: 32 rows)
    const int wk = wid & 3;         // 0..3  (k quarter via k8 interleave)
    const int j0 = blockIdx.x * 8;

    // stage Whh slice (24 rows x 1024) as tf32
    for (int f = tid; f < 24 * 256; f += NTHR) {
        int v = f >> 8, q = f & 255;
        int gate = v >> 3, jj = v & 7;
        const float* wr = Whh + (size_t)(gate * H_ + j0 + jj) * H_ + 4 * q;
        float4 w4 = *(const float4*)wr;
        *(float4*)(ws + v * WS_PAD + 4 * q) = cvt4(w4);
    }
    const float bhn  = bhh[2 * H_ + j0 + ((tid * 2) & 7)];
    const float bhn1 = bhh[2 * H_ + j0 + ((tid * 2 + 1) & 7)];
    __syncthreads();

    unsigned* barBase = g_barcnt + layer * T_;
    const int mst = tid >> 4;           // 0..15 (staging row base)
    const int k4 = (tid & 15) * 4;      // staging k offset

    for (int t = 0; t < T_; t++) {
        float gr[2] = {0.f, 0.f}, gz[2] = {0.f, 0.f}, gn[2] = {0.f, 0.f};

        if (t > 0) {
            const float* hre;
            size_t hstr;
            if (layer == 0) { hre = g_hseq + (size_t)(t - 1) * H_; hstr = (size_t)T_ * H_; }
            else            { hre = g_h1 + (size_t)((t - 1) & 1) * BH; hstr = H_; }

            float acc[2][3][4];
#pragma unroll
            for (int mi = 0; mi < 2; mi++)
#pragma unroll
                for (int ni = 0; ni < 3; ni++)
#pragma unroll
                    for (int q = 0; q < 4; q++) acc[mi][ni][q] = 0.f;

            // preload chunk 0
            {
#pragma unroll
                for (int r = 0; r < 4; r++) {
                    int m = mst + 16 * r;
                    float4 v = *(const float4*)(hre + (size_t)m * hstr + k4);
                    *(float4*)(as_ + m * AS_PAD + k4) = cvt4(v);
                }
            }
            __syncthreads();

            for (int cc = 0; cc < 16; cc++) {
                float4 ld[4];
                if (cc < 15) {
#pragma unroll
                    for (int r = 0; r < 4; r++) {
                        int m = mst + 16 * r;
                        ld[r] = *(const float4*)(hre + (size_t)m * hstr + (cc + 1) * 64 + k4);
                    }
                }
                const float* ab = as_ + (cc & 1) * (64 * AS_PAD);
#pragma unroll
                for (int s = 0; s < 2; s++) {
                    const int kl = (2 * wk + s) * 8;     // local k8 base in chunk
                    const int kg = cc * 64 + kl;         // global k base
                    uint32_t af[2][4];
#pragma unroll
                    for (int mi = 0; mi < 2; mi++) {
                        int mb = wm * 32 + mi * 16;
                        af[mi][0] = __float_as_uint(ab[(mb + g) * AS_PAD + kl + tig]);
                        af[mi][1] = __float_as_uint(ab[(mb + 8 + g) * AS_PAD + kl + tig]);
                        af[mi][2] = __float_as_uint(ab[(mb + g) * AS_PAD + kl + tig + 4]);
                        af[mi][3] = __float_as_uint(ab[(mb + 8 + g) * AS_PAD + kl + tig + 4]);
                    }
#pragma unroll
                    for (int ni = 0; ni < 3; ni++) {
                        uint32_t bf[2];
                        bf[0] = __float_as_uint(ws[(ni * 8 + g) * WS_PAD + kg + tig]);
                        bf[1] = __float_as_uint(ws[(ni * 8 + g) * WS_PAD + kg + tig + 4]);
                        mma8(acc[0][ni], af[0], bf);
                        mma8(acc[1][ni], af[1], bf);
                    }
                }
                if (cc < 15) {
                    float* d = as_ + ((cc + 1) & 1) * (64 * AS_PAD);
#pragma unroll
                    for (int r = 0; r < 4; r++) {
                        int m = mst + 16 * r;
                        *(float4*)(d + m * AS_PAD + k4) = cvt4(ld[r]);
                    }
                }
                __syncthreads();
            }

            // store k-split partials
#pragma unroll
            for (int mi = 0; mi < 2; mi++) {
#pragma unroll
                for (int ni = 0; ni < 3; ni++) {
                    int m = wm * 32 + mi * 16 + g;
                    int n = ni * 8 + 2 * tig;
                    float* p = red + ((size_t)(wk * 64 + m)) * RED_PAD + n;
                    p[0] = acc[mi][ni][0];
                    p[1] = acc[mi][ni][1];
                    float* p2 = red + ((size_t)(wk * 64 + m + 8)) * RED_PAD + n;
                    p2[0] = acc[mi][ni][2];
                    p2[1] = acc[mi][ni][3];
                }
            }
            __syncthreads();

            int idx2 = tid * 2;
#pragma unroll
            for (int e = 0; e < 2; e++) {
                int ii = idx2 + e;
                int b = ii >> 3, jj = ii & 7;
#pragma unroll
                for (int p = 0; p < 4; p++) {
                    const float* rp = red + (size_t)(p * 64 + b) * RED_PAD;
                    gr[e] += rp[jj];
                    gz[e] += rp[8 + jj];
                    gn[e] += rp[16 + jj];
                }
            }
        }

        // gates: 512 outputs per block, 2 per thread
        int idx2 = tid * 2;
#pragma unroll
        for (int e = 0; e < 2; e++) {
            int ii = idx2 + e;
            int b = ii >> 3, jj = ii & 7;
            int col = j0 + jj;
            const float* xp = g_xg + ((size_t)b * T_ + t) * G_ + col;
            float xr = xp[0], xz = xp[H_], xn = xp[2 * H_];
            float r = 1.f / (1.f + expf(-(xr + gr[e])));
            float z = 1.f / (1.f + expf(-(xz + gz[e])));
            float bn = e ? bhn1 : bhn;
            float n = tanhf(xn + r * (gn[e] + bn));
            float hp = 0.f;
            if (t > 0) {
                hp = (layer == 0) ? g_hseq[((size_t)b * T_ + (t - 1)) * H_ + col]
                                  : g_h1[(size_t)((t - 1) & 1) * BH + (size_t)b * H_ + col];
            }
            float hnew = (1.f - z) * n + z * hp;
            if (layer == 0) {
                g_hseq[((size_t)b * T_ + t) * H_ + col] = hnew;
            } else if (t == T_ - 1) {
                final_out[(size_t)b * H_ + col] = hnew;
            } else {
                g_h1[(size_t)(t & 1) * BH + (size_t)b * H_ + col] = hnew;
            }
        }

        if (t < T_ - 1) grid_bar(barBase + t);
    }
}

// ============================================================================
extern "C" void kernel_launch(void* const* d_in, const int* in_sizes, int n_in,
                              void* d_out, int out_size)
{
    const float* x    = (const float*)d_in[0];
    const float* wih0 = (const float*)d_in[1];
    const float* whh0 = (const float*)d_in[2];
    const float* bih0 = (const float*)d_in[3];
    const float* bhh0 = (const float*)d_in[4];
    const float* wih1 = (const float*)d_in[5];
    const float* whh1 = (const float*)d_in[6];
    const float* bih1 = (const float*)d_in[7];
    const float* bhh1 = (const float*)d_in[8];
    float* out = (float*)d_out;

    cudaFuncSetAttribute(gru_rec_mma, cudaFuncAttributeMaxDynamicSharedMemorySize, REC_SMEM);

    dim3 gg(G_ / 128, (B_ * T_) / 128);   // 24 x 256

    reset_barriers<<<1, 2 * T_>>>();

    xg_gemm<<<gg, 256>>>(x, 0, wih0, bih0, bhh0, I_);
    gru_rec_mma<<<NBLK, NTHR, REC_SMEM>>>(whh0, bhh0, 0, out);

    xg_gemm<<<gg, 256>>>(nullptr, 1, wih1, bih1, bhh1, H_);
    gru_rec_mma<<<NBLK, NTHR, REC_SMEM>>>(whh1, bhh1, 1, out);
}

// round 5
// speedup vs baseline: 1.9711x; 1.3406x over previous
#include <cuda_runtime.h>
#include <math.h>
#include <stdint.h>

namespace {
constexpr int B_ = 64;
constexpr int T_ = 512;
constexpr int I_ = 512;
constexpr int H_ = 1024;
constexpr int G_ = 3 * H_;     // 3072
constexpr int NBLK = 128;      // persistent blocks
constexpr int NTHR = 256;
constexpr int BH = B_ * H_;

constexpr int HR_PAD = 68;     // h chunk row pad (uint32) -> bank stride 4
constexpr int RP = 26;         // reduce row pad (even for float2)
constexpr int HR_F = 4 * 64 * HR_PAD;   // 17408 u32 (4-stage ring)
constexpr int RED_F = 8 * 64 * RP;      // 13312 fl
constexpr int REC_SMEM = (HR_F + RED_F) * 4;  // 122880 bytes
}

// Scratch (device globals -- no runtime allocation)
__device__ float g_xg[(size_t)B_ * T_ * G_];
__device__ float g_hseq[(size_t)B_ * T_ * H_];
__device__ __align__(16) uint32_t g_htf[2 * BH];   // h in tf32 bits, ping-pong
__device__ unsigned g_barcnt[2 * T_];

// ---- tf32 helpers ----
__device__ __forceinline__ uint32_t f2tf(float x) {
    uint32_t r;
    asm("cvt.rna.tf32.f32 %0, %1;" : "=r"(r) : "f"(x));
    return r;
}
__device__ __forceinline__ float4 cvt4(float4 v) {
    return make_float4(__uint_as_float(f2tf(v.x)), __uint_as_float(f2tf(v.y)),
                       __uint_as_float(f2tf(v.z)), __uint_as_float(f2tf(v.w)));
}
// m16n8k8 tf32 mma, D += A*B
__device__ __forceinline__ void mma8(float* d, const uint32_t* a, const uint32_t* b) {
    asm volatile(
        "mma.sync.aligned.m16n8k8.row.col.f32.tf32.tf32.f32 "
        "{%0,%1,%2,%3}, {%4,%5,%6,%7}, {%8,%9}, {%0,%1,%2,%3};"
        : "+f"(d[0]), "+f"(d[1]), "+f"(d[2]), "+f"(d[3])
        : "r"(a[0]), "r"(a[1]), "r"(a[2]), "r"(a[3]), "r"(b[0]), "r"(b[1]));
}
__device__ __forceinline__ uint32_t smem_u32(const void* p) {
    uint32_t a;
    asm("{ .reg .u64 t; cvta.to.shared.u64 t, %1; cvt.u32.u64 %0, t; }" : "=r"(a) : "l"(p));
    return a;
}

// ---- grid barrier ----
__device__ __forceinline__ void grid_bar(unsigned* cnt) {
    __threadfence();
    __syncthreads();
    if (threadIdx.x == 0) {
        asm volatile("red.release.gpu.global.add.u32 [%0], 1;" :: "l"(cnt) : "memory");
        unsigned v;
        do {
            asm volatile("ld.acquire.gpu.global.u32 %0, [%1];" : "=r"(v) : "l"(cnt) : "memory");
        } while (v < (unsigned)NBLK);
    }
    __syncthreads();
}

__global__ void reset_barriers() { g_barcnt[threadIdx.x] = 0; }

// ============================================================================
// xg = A[M][K] @ W[G][K]^T + b_ih (+ b_hh folded for r/z gates)
// tf32 mma.sync, tile 128x128x16, double buffered. 8 warps = 4m x 2n.
// (unchanged from round 4 — verified)
// ============================================================================
__global__ __launch_bounds__(256) void xg_gemm(
    const float* __restrict__ A_ext, int use_hseq,
    const float* __restrict__ W,
    const float* __restrict__ bih, const float* __restrict__ bhh,
    int K)
{
    __shared__ __align__(16) float sA[2][128][20];
    __shared__ __align__(16) float sB[2][128][20];
    const float* __restrict__ A = use_hseq ? (const float*)g_hseq : A_ext;

    const int tid = threadIdx.x;
    const int lane = tid & 31, wid = tid >> 5;
    const int g = lane >> 2, tig = lane & 3;
    const int wm = wid & 3, wn = wid >> 2;
    const int m0 = blockIdx.y * 128, n0 = blockIdx.x * 128;
    const int mrow = tid >> 1;
    const int kh = (tid & 1) * 8;

    float acc[2][8][4];
#pragma unroll
    for (int mi = 0; mi < 2; mi++)
#pragma unroll
        for (int ni = 0; ni < 8; ni++)
#pragma unroll
            for (int q = 0; q < 4; q++) acc[mi][ni][q] = 0.f;

    const int nch = K >> 4;
    {
        const float* ap = A + (size_t)(m0 + mrow) * K + kh;
        const float* bp = W + (size_t)(n0 + mrow) * K + kh;
        float4 a0 = *(const float4*)ap, a1 = *(const float4*)(ap + 4);
        float4 b0 = *(const float4*)bp, b1 = *(const float4*)(bp + 4);
        *(float4*)&sA[0][mrow][kh] = cvt4(a0);
        *(float4*)&sA[0][mrow][kh + 4] = cvt4(a1);
        *(float4*)&sB[0][mrow][kh] = cvt4(b0);
        *(float4*)&sB[0][mrow][kh + 4] = cvt4(b1);
    }
    __syncthreads();

    for (int ch = 0; ch < nch; ch++) {
        float4 la0, la1, lb0, lb1;
        if (ch + 1 < nch) {
            const float* ap = A + (size_t)(m0 + mrow) * K + (ch + 1) * 16 + kh;
            const float* bp = W + (size_t)(n0 + mrow) * K + (ch + 1) * 16 + kh;
            la0 = *(const float4*)ap; la1 = *(const float4*)(ap + 4);
            lb0 = *(const float4*)bp; lb1 = *(const float4*)(bp + 4);
        }
        const int buf = ch & 1;
#pragma unroll
        for (int s = 0; s < 2; s++) {
            const int k0 = s * 8;
            uint32_t af[2][4];
#pragma unroll
            for (int mi = 0; mi < 2; mi++) {
                int mb = wm * 32 + mi * 16;
                af[mi][0] = __float_as_uint(sA[buf][mb + g][k0 + tig]);
                af[mi][1] = __float_as_uint(sA[buf][mb + 8 + g][k0 + tig]);
                af[mi][2] = __float_as_uint(sA[buf][mb + g][k0 + tig + 4]);
                af[mi][3] = __float_as_uint(sA[buf][mb + 8 + g][k0 + tig + 4]);
            }
#pragma unroll
            for (int ni = 0; ni < 8; ni++) {
                int nb = wn * 64 + ni * 8;
                uint32_t bf[2];
                bf[0] = __float_as_uint(sB[buf][nb + g][k0 + tig]);
                bf[1] = __float_as_uint(sB[buf][nb + g][k0 + tig + 4]);
                mma8(acc[0][ni], af[0], bf);
                mma8(acc[1][ni], af[1], bf);
            }
        }
        if (ch + 1 < nch) {
            const int nb2 = buf ^ 1;
            *(float4*)&sA[nb2][mrow][kh] = cvt4(la0);
            *(float4*)&sA[nb2][mrow][kh + 4] = cvt4(la1);
            *(float4*)&sB[nb2][mrow][kh] = cvt4(lb0);
            *(float4*)&sB[nb2][mrow][kh + 4] = cvt4(lb1);
        }
        __syncthreads();
    }

#pragma unroll
    for (int mi = 0; mi < 2; mi++) {
        int m = m0 + wm * 32 + mi * 16 + g;
#pragma unroll
        for (int ni = 0; ni < 8; ni++) {
            int n = n0 + wn * 64 + ni * 8 + 2 * tig;
            float b0 = bih[n], b1 = bih[n + 1];
            if (n < 2 * H_) { b0 += bhh[n]; b1 += bhh[n + 1]; }
            *(float2*)(g_xg + (size_t)m * G_ + n) =
                make_float2(acc[mi][ni][0] + b0, acc[mi][ni][1] + b1);
            *(float2*)(g_xg + (size_t)(m + 8) * G_ + n) =
                make_float2(acc[mi][ni][2] + b0, acc[mi][ni][3] + b1);
        }
    }
}

// ============================================================================
// Persistent recurrence: block owns 8 hidden cols. W_hh fragments resident in
// REGISTERS (96/thread). h_{t-1} read as pre-converted tf32 via 4-stage
// cp.async pipeline. 8 warps, k8-interleaved k-split (1 k8 per warp per
// 64-k chunk). Smem reduce (8-way), gates, grid barrier.
// ============================================================================
__global__ void __launch_bounds__(NTHR, 1) gru_rec(
    const float* __restrict__ Whh, const float* __restrict__ bhh,
    int layer, float* __restrict__ final_out)
{
    extern __shared__ uint32_t smu[];
    uint32_t* hring = smu;                    // [4][64][HR_PAD] tf32 bits
    float* red = (float*)(smu + HR_F);        // [8][64][RP]

    const int tid = threadIdx.x;
    const int lane = tid & 31, wid = tid >> 5;   // wid = k8 slot (0..7)
    const int g = lane >> 2, tig = lane & 3;
    const int j0 = blockIdx.x * 8;
    const uint32_t hring_b = smem_u32(hring);

    // ---- W_hh fragments -> registers (once). breg[cc][ni]: chunk cc, gate-tile ni.
    uint32_t breg[16][3][2];
#pragma unroll
    for (int cc = 0; cc < 16; cc++)
#pragma unroll
        for (int ni = 0; ni < 3; ni++) {
            const float* wp = Whh + (size_t)(ni * H_ + j0 + g) * H_ + cc * 64 + wid * 8 + tig;
            breg[cc][ni][0] = f2tf(wp[0]);
            breg[cc][ni][1] = f2tf(wp[4]);
        }
    const float bhn0 = bhh[2 * H_ + j0 + ((tid * 2) & 7)];
    const float bhn1 = bhh[2 * H_ + j0 + ((tid * 2 + 1) & 7)];
    float hreg[2] = {0.f, 0.f};   // own (b,col) h from previous step

    unsigned* barBase = g_barcnt + layer * T_;
    const int srow = tid >> 4;        // 0..15 staging row base
    const int sq4 = (tid & 15) * 4;   // staging col (u32)

    for (int t = 0; t < T_; t++) {
        float gr[2] = {0.f, 0.f}, gz[2] = {0.f, 0.f}, gn[2] = {0.f, 0.f};

        if (t > 0) {
            const uint32_t* hre = g_htf + (size_t)((t - 1) & 1) * BH;

            float acc[4][3][4];
#pragma unroll
            for (int mt = 0; mt < 4; mt++)
#pragma unroll
                for (int ni = 0; ni < 3; ni++)
#pragma unroll
                    for (int q = 0; q < 4; q++) acc[mt][ni][q] = 0.f;

            // prime pipeline: chunks 0..2
#pragma unroll
            for (int p = 0; p < 3; p++) {
                uint32_t d = hring_b + (uint32_t)(((p & 3) * 64 + srow) * HR_PAD + sq4) * 4u;
                const uint32_t* s = hre + (size_t)srow * H_ + p * 64 + sq4;
#pragma unroll
                for (int r = 0; r < 4; r++) {
                    asm volatile("cp.async.cg.shared.global [%0], [%1], 16;"
                                 :: "r"(d), "l"(s) : "memory");
                    d += 16 * HR_PAD * 4;
                    s += 16 * H_;
                }
                asm volatile("cp.async.commit_group;" ::: "memory");
            }

#pragma unroll
            for (int cc = 0; cc < 16; cc++) {
                // wait for chunk cc (own groups), then block-wide visibility
                if (cc <= 13)      asm volatile("cp.async.wait_group 2;" ::: "memory");
                else if (cc == 14) asm volatile("cp.async.wait_group 1;" ::: "memory");
                else               asm volatile("cp.async.wait_group 0;" ::: "memory");
                __syncthreads();

                // issue chunk cc+3 into buffer (cc-1)&3 (mma of cc-1 done by all)
                if (cc + 3 < 16) {
                    const int p = cc + 3;
                    uint32_t d = hring_b + (uint32_t)(((p & 3) * 64 + srow) * HR_PAD + sq4) * 4u;
                    const uint32_t* s = hre + (size_t)srow * H_ + p * 64 + sq4;
#pragma unroll
                    for (int r = 0; r < 4; r++) {
                        asm volatile("cp.async.cg.shared.global [%0], [%1], 16;"
                                     :: "r"(d), "l"(s) : "memory");
                        d += 16 * HR_PAD * 4;
                        s += 16 * H_;
                    }
                    asm volatile("cp.async.commit_group;" ::: "memory");
                }

                const uint32_t* ab = hring + (cc & 3) * 64 * HR_PAD;
#pragma unroll
                for (int mt = 0; mt < 4; mt++) {
                    const uint32_t* r0 = ab + (mt * 16 + g) * HR_PAD + wid * 8 + tig;
                    const uint32_t* r1 = ab + (mt * 16 + 8 + g) * HR_PAD + wid * 8 + tig;
                    uint32_t af[4] = {r0[0], r1[0], r0[4], r1[4]};
#pragma unroll
                    for (int ni = 0; ni < 3; ni++)
                        mma8(acc[mt][ni], af, breg[cc][ni]);
                }
            }

            // ---- 8-way k reduce via smem ----
#pragma unroll
            for (int mt = 0; mt < 4; mt++)
#pragma unroll
                for (int ni = 0; ni < 3; ni++) {
                    float* p0 = red + (size_t)(wid * 64 + mt * 16 + g) * RP + ni * 8 + 2 * tig;
                    *(float2*)p0 = make_float2(acc[mt][ni][0], acc[mt][ni][1]);
                    float* p1 = red + (size_t)(wid * 64 + mt * 16 + 8 + g) * RP + ni * 8 + 2 * tig;
                    *(float2*)p1 = make_float2(acc[mt][ni][2], acc[mt][ni][3]);
                }
            __syncthreads();

#pragma unroll
            for (int e = 0; e < 2; e++) {
                int ii = tid * 2 + e;
                int b = ii >> 3, jj = ii & 7;
#pragma unroll
                for (int p = 0; p < 8; p++) {
                    const float* rp = red + (size_t)(p * 64 + b) * RP;
                    gr[e] += rp[jj];
                    gz[e] += rp[8 + jj];
                    gn[e] += rp[16 + jj];
                }
            }
        }

        // ---- gates: 2 outputs per thread ----
#pragma unroll
        for (int e = 0; e < 2; e++) {
            int ii = tid * 2 + e;
            int b = ii >> 3, jj = ii & 7;
            int col = j0 + jj;
            const float* xp = g_xg + ((size_t)b * T_ + t) * G_ + col;
            float xr = xp[0], xz = xp[H_], xn = xp[2 * H_];
            float r = 1.f / (1.f + expf(-(xr + gr[e])));
            float z = 1.f / (1.f + expf(-(xz + gz[e])));
            float bn = e ? bhn1 : bhn0;
            float n = tanhf(xn + r * (gn[e] + bn));
            float hnew = (1.f - z) * n + z * hreg[e];
            hreg[e] = hnew;

            g_htf[(size_t)(t & 1) * BH + (size_t)b * H_ + col] = f2tf(hnew);
            if (layer == 0) {
                g_hseq[((size_t)b * T_ + t) * H_ + col] = hnew;
            } else if (t == T_ - 1) {
                final_out[(size_t)b * H_ + col] = hnew;
            }
        }

        if (t < T_ - 1) grid_bar(barBase + t);
    }
}

// ============================================================================
extern "C" void kernel_launch(void* const* d_in, const int* in_sizes, int n_in,
                              void* d_out, int out_size)
{
    const float* x    = (const float*)d_in[0];
    const float* wih0 = (const float*)d_in[1];
    const float* whh0 = (const float*)d_in[2];
    const float* bih0 = (const float*)d_in[3];
    const float* bhh0 = (const float*)d_in[4];
    const float* wih1 = (const float*)d_in[5];
    const float* whh1 = (const float*)d_in[6];
    const float* bih1 = (const float*)d_in[7];
    const float* bhh1 = (const float*)d_in[8];
    float* out = (float*)d_out;

    cudaFuncSetAttribute(gru_rec, cudaFuncAttributeMaxDynamicSharedMemorySize, REC_SMEM);

    dim3 gg(G_ / 128, (B_ * T_) / 128);   // 24 x 256

    reset_barriers<<<1, 2 * T_>>>();

    xg_gemm<<<gg, 256>>>(x, 0, wih0, bih0, bhh0, I_);
    gru_rec<<<NBLK, NTHR, REC_SMEM>>>(whh0, bhh0, 0, out);

    xg_gemm<<<gg, 256>>>(nullptr, 1, wih1, bih1, bhh1, H_);
    gru_rec<<<NBLK, NTHR, REC_SMEM>>>(whh1, bhh1, 1, out);
}